// round 13
// baseline (speedup 1.0000x reference)
#include <cuda_runtime.h>
#include <cuda_fp16.h>
#include <cstdint>

// HyperspectralAttention collapses (per-head dim == 1 => softmax == 1) to
//   out = W_proj @ ( illu * ( (0.6*W_v_spec + 0.4*W_v_spat) @ x ) )
// Two 64 x 262144 x 64 GEMMs on mma.sync, all operands single fp16
// (rel_err ~4e-4 < 1e-3 gate).
//
// R13: full-tile latency coverage for both input streams.
//  - X(t+1): 32 raw scalar LDGs issued at tile TOP into xf[32]; packed to
//    half2 frags only at tile END (pack no longer chains on the loads).
//  - illu: double-buffered per-warp smem; illu(t+1) cp.async issued at tile
//    top, cp_wait<1> before the epilogue waits only on illu(t).
// Otherwise R12 structure: barrier-free per-warp 16-px pipelines, swapped
// GEMM2 (acc1 reused as B-frag, float2 stores), 256 thr, 2 CTAs/SM.

#define TPB 256
#define NWARPS 8
#define NWT 16384            // 16-px warp tiles

// smem: W 16KB + 8 warps x 2 illu buffers x 5120B
#define SM_WM  0u
#define SM_WP  8192u
#define SM_ILL 16384u
#define ILL_BSZ 5120u
#define ILL_WSZ (2u * ILL_BSZ)
#define SM_TOTAL (16384 + NWARPS * 2 * 5120)   // 98304

__device__ __forceinline__ uint32_t smem_u32(const void* p) {
    uint32_t a;
    asm("{ .reg .u64 t; cvta.to.shared.u64 t, %1; cvt.u32.u64 %0, t; }"
        : "=r"(a) : "l"(p));
    return a;
}
__device__ __forceinline__ void cp_async16(uint32_t dst, const void* src) {
    asm volatile("cp.async.cg.shared.global [%0], [%1], 16;"
                 :: "r"(dst), "l"(src) : "memory");
}
__device__ __forceinline__ void cp_commit() {
    asm volatile("cp.async.commit_group;" ::: "memory");
}
template <int N>
__device__ __forceinline__ void cp_wait() {
    asm volatile("cp.async.wait_group %0;" :: "n"(N) : "memory");
}
__device__ __forceinline__ void ldsm4(uint32_t addr, uint32_t r[4]) {
    asm volatile("ldmatrix.sync.aligned.m8n8.x4.shared.b16 {%0,%1,%2,%3}, [%4];"
                 : "=r"(r[0]), "=r"(r[1]), "=r"(r[2]), "=r"(r[3]) : "r"(addr));
}
__device__ __forceinline__ void mma16816(float c[4], const uint32_t a[4],
                                         uint32_t b0, uint32_t b1) {
    asm volatile("mma.sync.aligned.m16n8k16.row.col.f32.f16.f16.f32 "
                 "{%0,%1,%2,%3}, {%4,%5,%6,%7}, {%8,%9}, {%0,%1,%2,%3};"
                 : "+f"(c[0]), "+f"(c[1]), "+f"(c[2]), "+f"(c[3])
                 : "r"(a[0]), "r"(a[1]), "r"(a[2]), "r"(a[3]), "r"(b0), "r"(b1));
}
__device__ __forceinline__ uint32_t packh2(float v0, float v1) {
    __half2 hp = __floats2half2_rn(v0, v1);
    return *reinterpret_cast<uint32_t*>(&hp);
}
__device__ __forceinline__ float ldgnc(const float* p) {
    float v;
    asm volatile("ld.global.nc.f32 %0, [%1];" : "=f"(v) : "l"(p));
    return v;
}

// GEMM1 B-frag ldmatrix addr on W[o][c]: groups = n0k0,n0k8,n8k0,n8k8
__device__ __forceinline__ uint32_t waddrB(uint32_t sbW, int ntp, int kc, int lane) {
    const int o  = ntp * 16 + ((lane >> 4) & 1) * 8 + (lane & 7);
    const int cb = kc * 32 + ((lane >> 3) & 1) * 16;
    return sbW + (uint32_t)(o * 128) + (uint32_t)(cb ^ ((o & 7) << 4));
}
// GEMM2 A-frag ldmatrix addr on W[o'][o]: groups = m0k0,m8k0,m0k8,m8k8
__device__ __forceinline__ uint32_t waddrA(uint32_t sbW, int mtp, int kc, int lane) {
    const int o  = mtp * 16 + ((lane >> 3) & 1) * 8 + (lane & 7);
    const int cb = kc * 32 + ((lane >> 4) & 1) * 16;
    return sbW + (uint32_t)(o * 128) + (uint32_t)(cb ^ ((o & 7) << 4));
}

__device__ __forceinline__ size_t tile_base(int t) {
    return (size_t)(t >> 12) * 4194304 + (size_t)(t & 4095) * 16;
}

// 32 raw scalar LDGs (this lane's A-frag elements for all 4 k-chunks)
__device__ __forceinline__ void ldx_raw(const float* xb, int tq, int g, float v[32]) {
    #pragma unroll
    for (int kc = 0; kc < 4; kc++) {
        const float* p0 = xb + (size_t)(kc * 16 + 2 * tq) * 65536 + g;
        v[kc * 8 + 0] = ldgnc(p0);           v[kc * 8 + 1] = ldgnc(p0 + 65536);
        v[kc * 8 + 2] = ldgnc(p0 + 8);       v[kc * 8 + 3] = ldgnc(p0 + 65536 + 8);
        const float* p1 = p0 + (size_t)8 * 65536;
        v[kc * 8 + 4] = ldgnc(p1);           v[kc * 8 + 5] = ldgnc(p1 + 65536);
        v[kc * 8 + 6] = ldgnc(p1 + 8);       v[kc * 8 + 7] = ldgnc(p1 + 65536 + 8);
    }
}
__device__ __forceinline__ void pack_x(const float v[32], uint32_t xh[4][4]) {
    #pragma unroll
    for (int kc = 0; kc < 4; kc++) {
        xh[kc][0] = packh2(v[kc * 8 + 0], v[kc * 8 + 1]);  // (m=g,   k lo pair)
        xh[kc][1] = packh2(v[kc * 8 + 2], v[kc * 8 + 3]);  // (m=g+8, k lo pair)
        xh[kc][2] = packh2(v[kc * 8 + 4], v[kc * 8 + 5]);  // (m=g,   k hi pair)
        xh[kc][3] = packh2(v[kc * 8 + 6], v[kc * 8 + 7]);  // (m=g+8, k hi pair)
    }
}
__device__ __forceinline__ void issue_ill(const float* illu, int t, int lane,
                                          uint32_t dstBuf) {
    const float* ib = illu + tile_base(t);
    #pragma unroll
    for (int k = 0; k < 8; k++) {
        const int j = lane + k * 32, c = j >> 2, q = j & 3;
        cp_async16(dstBuf + (uint32_t)(c * 80 + q * 16),
                   ib + (size_t)c * 65536 + q * 4);
    }
}

__global__ __launch_bounds__(TPB, 2) void fused_h4(
    const float* __restrict__ x, const float* __restrict__ illu,
    const float* __restrict__ wvspec, const float* __restrict__ wvspat,
    const float* __restrict__ wproj, float* __restrict__ out)
{
    extern __shared__ char smem[];
    const uint32_t sb = smem_u32(smem);
    const int tid = threadIdx.x, lane = tid & 31, w = tid >> 5;
    const int g = lane >> 2, tq = lane & 3;

    // ---- weights once per CTA (fp16, [o][c] 128B swizzled rows) ----
    for (int i = tid; i < 4096; i += TPB) {
        const int o = i >> 6, c = i & 63;
        const uint32_t off = (uint32_t)(o * 128) +
                             (((uint32_t)(2 * c)) ^ ((uint32_t)(o & 7) << 4));
        *(__half*)(smem + SM_WM + off) =
            __float2half_rn(0.6f * wvspec[i] + 0.4f * wvspat[i]);
        *(__half*)(smem + SM_WP + off) = __float2half_rn(wproj[i]);
    }
    __syncthreads();   // only CTA-wide barrier in the kernel

    const uint32_t sbWM = sb + SM_WM, sbWP = sb + SM_WP;
    const uint32_t sbIL = sb + SM_ILL + (uint32_t)w * ILL_WSZ;

    int t = blockIdx.x * NWARPS + w;
    const int stride = gridDim.x * NWARPS;
    if (t >= NWT) return;

    uint32_t xh[4][4];
    int buf = 0;
    {   // prologue: X(t0) load+pack (one-time stall), illu(t0) -> buf 0
        float v[32];
        ldx_raw(x + tile_base(t), tq, g, v);
        issue_ill(illu, t, lane, sbIL);
        cp_commit();
        pack_x(v, xh);
    }

    while (t < NWT) {
        const int tn = t + stride;

        // ---- tile-top prefetch: X(t+1) raw regs, illu(t+1) other buffer ----
        float xf[32];
        if (tn < NWT) {
            ldx_raw(x + tile_base(tn), tq, g, xf);
            issue_ill(illu, tn, lane, sbIL + (uint32_t)(buf ^ 1) * ILL_BSZ);
        }
        cp_commit();     // unconditional: keeps group counting exact

        // ---- GEMM1: acc1[px16][o64] = X^T @ Wm^T ----
        float acc1[8][4];
        #pragma unroll
        for (int nt = 0; nt < 8; nt++)
            #pragma unroll
            for (int q = 0; q < 4; q++) acc1[nt][q] = 0.0f;

        #pragma unroll
        for (int kc = 0; kc < 4; kc++) {
            uint32_t a[4] = { xh[kc][0], xh[kc][1], xh[kc][2], xh[kc][3] };
            #pragma unroll
            for (int ntp = 0; ntp < 4; ntp++) {
                uint32_t b[4];
                ldsm4(waddrB(sbWM, ntp, kc, lane), b);
                mma16816(acc1[2 * ntp],     a, b[0], b[1]);
                mma16816(acc1[2 * ntp + 1], a, b[2], b[3]);
            }
        }

        cp_wait<1>();    // illu(t) complete; illu(t+1) group may still fly
        __syncwarp();    // other lanes' illu(t) visible

        // ---- GEMM2 (swapped): acc2[o'64][px16] = Wp @ (illu * D1) ----
        const float* ILF = (const float*)(smem + SM_ILL + (size_t)w * ILL_WSZ
                                          + (size_t)buf * ILL_BSZ);
        float acc2[4][2][4];
        #pragma unroll
        for (int mt = 0; mt < 4; mt++)
            #pragma unroll
            for (int nt = 0; nt < 2; nt++)
                #pragma unroll
                for (int q = 0; q < 4; q++) acc2[mt][nt][q] = 0.0f;

        #pragma unroll
        for (int kc = 0; kc < 4; kc++) {
            const int nA = 2 * kc, nB = 2 * kc + 1;
            const int o0 = nA * 8 + 2 * tq;
            const int o8 = nB * 8 + 2 * tq;
            uint32_t blo[2], bhi[2];
            blo[0] = packh2(acc1[nA][0] * ILF[o0 * 20 + g],
                            acc1[nA][1] * ILF[(o0 + 1) * 20 + g]);
            blo[1] = packh2(acc1[nB][0] * ILF[o8 * 20 + g],
                            acc1[nB][1] * ILF[(o8 + 1) * 20 + g]);
            bhi[0] = packh2(acc1[nA][2] * ILF[o0 * 20 + g + 8],
                            acc1[nA][3] * ILF[(o0 + 1) * 20 + g + 8]);
            bhi[1] = packh2(acc1[nB][2] * ILF[o8 * 20 + g + 8],
                            acc1[nB][3] * ILF[(o8 + 1) * 20 + g + 8]);
            #pragma unroll
            for (int mt = 0; mt < 4; mt++) {
                uint32_t aW[4];
                ldsm4(waddrA(sbWP, mt, kc, lane), aW);
                mma16816(acc2[mt][0], aW, blo[0], blo[1]);
                mma16816(acc2[mt][1], aW, bhi[0], bhi[1]);
            }
        }

        // ---- store: acc2 (m=o', n=px) -> float2 per lane ----
        {
            float* obp = out + tile_base(t);
            #pragma unroll
            for (int mt = 0; mt < 4; mt++)
                #pragma unroll
                for (int nt = 0; nt < 2; nt++) {
                    const int o0 = mt * 16 + g;
                    const int px = nt * 8 + 2 * tq;
                    *(float2*)(obp + (size_t)o0 * 65536 + px) =
                        make_float2(acc2[mt][nt][0], acc2[mt][nt][1]);
                    *(float2*)(obp + (size_t)(o0 + 8) * 65536 + px) =
                        make_float2(acc2[mt][nt][2], acc2[mt][nt][3]);
                }
        }

        // ---- tile-end: pack X(t+1) (loads long since landed) ----
        if (tn < NWT) pack_x(xf, xh);
        buf ^= 1;
        t = tn;
    }
}

extern "C" void kernel_launch(void* const* d_in, const int* in_sizes, int n_in,
                              void* d_out, int out_size)
{
    const float* x      = (const float*)d_in[0];
    const float* illu   = (const float*)d_in[1];
    const float* wvspec = (const float*)d_in[4];
    const float* wvspat = (const float*)d_in[7];
    const float* wproj  = (const float*)d_in[10];
    float* out = (float*)d_out;

    int dev = 0, sms = 148;
    cudaGetDevice(&dev);
    cudaDeviceGetAttribute(&sms, cudaDevAttrMultiProcessorCount, dev);
    if (sms < 1) sms = 148;
    int grid = 2 * sms;
    if (grid * NWARPS > NWT) grid = NWT / NWARPS;

    cudaFuncSetAttribute(fused_h4, cudaFuncAttributeMaxDynamicSharedMemorySize,
                         SM_TOTAL);
    fused_h4<<<grid, TPB, SM_TOTAL>>>(x, illu, wvspec, wvspat, wproj, out);
}

// round 15
// speedup vs baseline: 1.0267x; 1.0267x over previous
#include <cuda_runtime.h>
#include <cuda_fp16.h>
#include <cstdint>

// HyperspectralAttention collapses (per-head dim == 1 => softmax == 1) to
//   out = W_proj @ ( illu * ( (0.6*W_v_spec + 0.4*W_v_spat) @ x ) )
// Two 64 x 262144 x 64 GEMMs on mma.sync, all operands single fp16
// (rel_err ~4e-4 < 1e-3 gate).
//
// R14b (compile fix of R14): WEIGHTS RESIDENT IN REGISTERS. L1-wavefront
// audit showed ~30% of L1 traffic was re-ldsm'ing constant weights every
// tile. 1 CTA x 256 thr per SM (255-reg budget): Wm held as 16 B-frags +
// Wp as 16 A-frags (128 regs), loaded once via ldsm at startup; the
// per-tile loop has ZERO weight smem traffic. Otherwise R12 structure:
// barrier-free per-warp 16-px pipelines, X direct-LDG prefetch inside
// GEMM1, swapped GEMM2 (acc1 reused as B-frag, float2 stores), illu
// single-buffer cp.async per warp.

#define TPB 256
#define NWARPS 8
#define NWT 16384            // 16-px warp tiles

// smem: W 16KB + 8 per-warp illu buffers [64][20]f32 (5120B each)
#define SM_WM  0u
#define SM_WP  8192u
#define SM_ILL 16384u
#define ILL_WSZ 5120u
#define SM_TOTAL (16384 + NWARPS * 5120)

__device__ __forceinline__ uint32_t smem_u32(const void* p) {
    uint32_t a;
    asm("{ .reg .u64 t; cvta.to.shared.u64 t, %1; cvt.u32.u64 %0, t; }"
        : "=r"(a) : "l"(p));
    return a;
}
__device__ __forceinline__ void cp_async16(uint32_t dst, const void* src) {
    asm volatile("cp.async.cg.shared.global [%0], [%1], 16;"
                 :: "r"(dst), "l"(src) : "memory");
}
__device__ __forceinline__ void cp_commit() {
    asm volatile("cp.async.commit_group;" ::: "memory");
}
template <int N>
__device__ __forceinline__ void cp_wait() {
    asm volatile("cp.async.wait_group %0;" :: "n"(N) : "memory");
}
__device__ __forceinline__ void ldsm4(uint32_t addr, uint32_t r[4]) {
    asm volatile("ldmatrix.sync.aligned.m8n8.x4.shared.b16 {%0,%1,%2,%3}, [%4];"
                 : "=r"(r[0]), "=r"(r[1]), "=r"(r[2]), "=r"(r[3]) : "r"(addr));
}
__device__ __forceinline__ void mma16816(float c[4], const uint32_t a[4],
                                         uint32_t b0, uint32_t b1) {
    asm volatile("mma.sync.aligned.m16n8k16.row.col.f32.f16.f16.f32 "
                 "{%0,%1,%2,%3}, {%4,%5,%6,%7}, {%8,%9}, {%0,%1,%2,%3};"
                 : "+f"(c[0]), "+f"(c[1]), "+f"(c[2]), "+f"(c[3])
                 : "r"(a[0]), "r"(a[1]), "r"(a[2]), "r"(a[3]), "r"(b0), "r"(b1));
}
__device__ __forceinline__ uint32_t packh2(float v0, float v1) {
    __half2 hp = __floats2half2_rn(v0, v1);
    return *reinterpret_cast<uint32_t*>(&hp);
}
__device__ __forceinline__ float ldgnc(const float* p) {
    float v;
    asm volatile("ld.global.nc.f32 %0, [%1];" : "=f"(v) : "l"(p));
    return v;
}

// GEMM1 B-frag ldsm addr on W[o][c]: groups = n0k0,n0k8,n8k0,n8k8
__device__ __forceinline__ uint32_t waddrB(uint32_t sbW, int ntp, int kc, int lane) {
    const int o  = ntp * 16 + ((lane >> 4) & 1) * 8 + (lane & 7);
    const int cb = kc * 32 + ((lane >> 3) & 1) * 16;
    return sbW + (uint32_t)(o * 128) + (uint32_t)(cb ^ ((o & 7) << 4));
}
// GEMM2 A-frag ldsm addr on W[o'][o]: groups = m0k0,m8k0,m0k8,m8k8
__device__ __forceinline__ uint32_t waddrA(uint32_t sbW, int mtp, int kc, int lane) {
    const int o  = mtp * 16 + ((lane >> 3) & 1) * 8 + (lane & 7);
    const int cb = kc * 32 + ((lane >> 4) & 1) * 16;
    return sbW + (uint32_t)(o * 128) + (uint32_t)(cb ^ ((o & 7) << 4));
}

__device__ __forceinline__ size_t tile_base(int t) {
    return (size_t)(t >> 12) * 4194304 + (size_t)(t & 4095) * 16;
}

// load this lane's 8 X scalars for k-chunk kc, convert to A-frag half2 x4
__device__ __forceinline__ void ldxh(const float* xb, int kc, int tq, int g,
                                     uint32_t v[4]) {
    const float* p0 = xb + (size_t)(kc * 16 + 2 * tq) * 65536 + g;
    const float a0 = ldgnc(p0),             a1 = ldgnc(p0 + 65536);
    const float a2 = ldgnc(p0 + 8),         a3 = ldgnc(p0 + 65536 + 8);
    const float* p1 = p0 + (size_t)8 * 65536;
    const float a4 = ldgnc(p1),             a5 = ldgnc(p1 + 65536);
    const float a6 = ldgnc(p1 + 8),         a7 = ldgnc(p1 + 65536 + 8);
    v[0] = packh2(a0, a1);   // (m=g,   k lo pair)
    v[1] = packh2(a2, a3);   // (m=g+8, k lo pair)
    v[2] = packh2(a4, a5);   // (m=g,   k hi pair)
    v[3] = packh2(a6, a7);   // (m=g+8, k hi pair)
}

__global__ __launch_bounds__(TPB, 1) void fused_h5(
    const float* __restrict__ x, const float* __restrict__ illu,
    const float* __restrict__ wvspec, const float* __restrict__ wvspat,
    const float* __restrict__ wproj, float* __restrict__ out)
{
    extern __shared__ char smem[];
    const uint32_t sb = smem_u32(smem);
    const int tid = threadIdx.x, lane = tid & 31, w = tid >> 5;
    const int g = lane >> 2, tq = lane & 3;

    // ---- weights -> smem fp16 (once), then into register fragments ----
    for (int i = tid; i < 4096; i += TPB) {
        const int o = i >> 6, c = i & 63;
        const uint32_t off = (uint32_t)(o * 128) +
                             (((uint32_t)(2 * c)) ^ ((uint32_t)(o & 7) << 4));
        *(__half*)(smem + SM_WM + off) =
            __float2half_rn(0.6f * wvspec[i] + 0.4f * wvspat[i]);
        *(__half*)(smem + SM_WP + off) = __float2half_rn(wproj[i]);
    }
    __syncthreads();

    uint32_t wm[16][4];   // Wm B-frags: [kc*4+ntp]
    uint32_t wp[16][4];   // Wp A-frags: [kc*4+mt]
    #pragma unroll
    for (int kc = 0; kc < 4; kc++)
        #pragma unroll
        for (int p = 0; p < 4; p++) {
            ldsm4(waddrB(sb + SM_WM, p, kc, lane), wm[kc * 4 + p]);
            ldsm4(waddrA(sb + SM_WP, p, kc, lane), wp[kc * 4 + p]);
        }

    const uint32_t sbIL = sb + SM_ILL + (uint32_t)w * ILL_WSZ;
    const float* ILF = (const float*)(smem + SM_ILL + (size_t)w * ILL_WSZ);

    int t = blockIdx.x * NWARPS + w;
    const int stride = gridDim.x * NWARPS;
    if (t >= NWT) return;

    uint32_t xh[4][4];
    {   // prologue: X(t) -> half2 frags + illu(t) cp.async
        const float* xb = x + tile_base(t);
        #pragma unroll
        for (int kc = 0; kc < 4; kc++) ldxh(xb, kc, tq, g, xh[kc]);
        const float* ib = illu + tile_base(t);
        #pragma unroll
        for (int k = 0; k < 8; k++) {
            const int j = lane + k * 32, c = j >> 2, q = j & 3;
            cp_async16(sbIL + (uint32_t)(c * 80 + q * 16),
                       ib + (size_t)c * 65536 + q * 4);
        }
        cp_commit();
    }

    while (t < NWT) {
        const int tn = t + stride;
        const float* xbn = (tn < NWT) ? x + tile_base(tn) : x;

        // ---- GEMM1: acc1[px16][o64] = X^T @ Wm^T (weights in regs) ----
        float acc1[8][4];
        #pragma unroll
        for (int nt = 0; nt < 8; nt++)
            #pragma unroll
            for (int q = 0; q < 4; q++) acc1[nt][q] = 0.0f;

        #pragma unroll
        for (int kc = 0; kc < 4; kc++) {
            uint32_t a[4] = { xh[kc][0], xh[kc][1], xh[kc][2], xh[kc][3] };
            #pragma unroll
            for (int ntp = 0; ntp < 4; ntp++) {
                const uint32_t* b = wm[kc * 4 + ntp];
                mma16816(acc1[2 * ntp],     a, b[0], b[1]);
                mma16816(acc1[2 * ntp + 1], a, b[2], b[3]);
            }
            if (tn < NWT) ldxh(xbn, kc, tq, g, xh[kc]);  // prefetch, regs free
        }

        cp_wait<0>();
        __syncwarp();          // other lanes' illu(t) cp.async visible

        // ---- GEMM2 (swapped): acc2[o'64][px16] = Wp @ (illu * D1) ----
        // acc1 IS the B-frag source: [0][1] -> k-pair @ n=px=g,
        //                            [2][3] -> same k-pair @ n=g+8.
        float acc2[4][2][4];
        #pragma unroll
        for (int mt = 0; mt < 4; mt++)
            #pragma unroll
            for (int nt = 0; nt < 2; nt++)
                #pragma unroll
                for (int q = 0; q < 4; q++) acc2[mt][nt][q] = 0.0f;

        #pragma unroll
        for (int kc = 0; kc < 4; kc++) {
            const int nA = 2 * kc, nB = 2 * kc + 1;
            const int o0 = nA * 8 + 2 * tq;
            const int o8 = nB * 8 + 2 * tq;
            uint32_t blo[2], bhi[2];
            blo[0] = packh2(acc1[nA][0] * ILF[o0 * 20 + g],
                            acc1[nA][1] * ILF[(o0 + 1) * 20 + g]);
            blo[1] = packh2(acc1[nB][0] * ILF[o8 * 20 + g],
                            acc1[nB][1] * ILF[(o8 + 1) * 20 + g]);
            bhi[0] = packh2(acc1[nA][2] * ILF[o0 * 20 + g + 8],
                            acc1[nA][3] * ILF[(o0 + 1) * 20 + g + 8]);
            bhi[1] = packh2(acc1[nB][2] * ILF[o8 * 20 + g + 8],
                            acc1[nB][3] * ILF[(o8 + 1) * 20 + g + 8]);
            #pragma unroll
            for (int mt = 0; mt < 4; mt++) {
                const uint32_t* aW = wp[kc * 4 + mt];
                mma16816(acc2[mt][0], aW, blo[0], blo[1]);
                mma16816(acc2[mt][1], aW, bhi[0], bhi[1]);
            }
        }
        __syncwarp();          // all lanes done reading illu(t)

        // prefetch illu(t+1) (single buffer: safe only after reads done)
        if (tn < NWT) {
            const float* ib = illu + tile_base(tn);
            #pragma unroll
            for (int k = 0; k < 8; k++) {
                const int j = lane + k * 32, c = j >> 2, q = j & 3;
                cp_async16(sbIL + (uint32_t)(c * 80 + q * 16),
                           ib + (size_t)c * 65536 + q * 4);
            }
            cp_commit();
        }

        // ---- store: acc2 (m=o', n=px) -> float2 per lane ----
        {
            float* obp = out + tile_base(t);
            #pragma unroll
            for (int mt = 0; mt < 4; mt++)
                #pragma unroll
                for (int nt = 0; nt < 2; nt++) {
                    const int o0 = mt * 16 + g;
                    const int px = nt * 8 + 2 * tq;
                    *(float2*)(obp + (size_t)o0 * 65536 + px) =
                        make_float2(acc2[mt][nt][0], acc2[mt][nt][1]);
                    *(float2*)(obp + (size_t)(o0 + 8) * 65536 + px) =
                        make_float2(acc2[mt][nt][2], acc2[mt][nt][3]);
                }
        }
        t = tn;
    }
}

extern "C" void kernel_launch(void* const* d_in, const int* in_sizes, int n_in,
                              void* d_out, int out_size)
{
    const float* x      = (const float*)d_in[0];
    const float* illu   = (const float*)d_in[1];
    const float* wvspec = (const float*)d_in[4];
    const float* wvspat = (const float*)d_in[7];
    const float* wproj  = (const float*)d_in[10];
    float* out = (float*)d_out;

    int dev = 0, sms = 148;
    cudaGetDevice(&dev);
    cudaDeviceGetAttribute(&sms, cudaDevAttrMultiProcessorCount, dev);
    if (sms < 1) sms = 148;
    int grid = sms;                      // 1 CTA/SM (full register budget)
    if (grid * NWARPS > NWT) grid = NWT / NWARPS;

    cudaFuncSetAttribute(fused_h5, cudaFuncAttributeMaxDynamicSharedMemorySize,
                         SM_TOTAL);
    fused_h5<<<grid, TPB, SM_TOTAL>>>(x, illu, wvspec, wvspat, wproj, out);
}

// round 16
// speedup vs baseline: 1.0787x; 1.0506x over previous
#include <cuda_runtime.h>
#include <cuda_fp16.h>
#include <cstdint>

// HyperspectralAttention collapses (per-head dim == 1 => softmax == 1) to
//   out = W_proj @ ( illu * ( (0.6*W_v_spec + 0.4*W_v_spat) @ x ) )
// Two 64 x 262144 x 64 GEMMs on mma.sync, all operands single fp16
// (rel_err ~4e-4 < 1e-3 gate).
//
// R16: HALF weight residency + 50% more warps. R15 proved weight-in-regs
// cuts L1 to 41% but the 255-reg cap left only 8 warps (issue 12.5%,
// latency-bound at DRAM 50%). Now: Wp stays register-resident (64 regs,
// used in GEMM2), Wm re-ldsm'd during GEMM1 (LDS pipe idle there anyway).
// Peak live ~150 regs -> 384 thr x 168 regs, 12 warps/SM. Otherwise R12
// structure: barrier-free per-warp 16-px pipelines, X direct-LDG prefetch
// inside GEMM1, swapped GEMM2 (acc1 reused as B-frag, float2 stores),
// illu single-buffer cp.async per warp.

#define TPB 384
#define NWARPS 12
#define NWT 16384            // 16-px warp tiles

// smem: W 16KB + 12 per-warp illu buffers [64][20]f32 (5120B each)
#define SM_WM  0u
#define SM_WP  8192u
#define SM_ILL 16384u
#define ILL_WSZ 5120u
#define SM_TOTAL (16384 + NWARPS * 5120)

__device__ __forceinline__ uint32_t smem_u32(const void* p) {
    uint32_t a;
    asm("{ .reg .u64 t; cvta.to.shared.u64 t, %1; cvt.u32.u64 %0, t; }"
        : "=r"(a) : "l"(p));
    return a;
}
__device__ __forceinline__ void cp_async16(uint32_t dst, const void* src) {
    asm volatile("cp.async.cg.shared.global [%0], [%1], 16;"
                 :: "r"(dst), "l"(src) : "memory");
}
__device__ __forceinline__ void cp_commit() {
    asm volatile("cp.async.commit_group;" ::: "memory");
}
template <int N>
__device__ __forceinline__ void cp_wait() {
    asm volatile("cp.async.wait_group %0;" :: "n"(N) : "memory");
}
__device__ __forceinline__ void ldsm4(uint32_t addr, uint32_t r[4]) {
    asm volatile("ldmatrix.sync.aligned.m8n8.x4.shared.b16 {%0,%1,%2,%3}, [%4];"
                 : "=r"(r[0]), "=r"(r[1]), "=r"(r[2]), "=r"(r[3]) : "r"(addr));
}
__device__ __forceinline__ void mma16816(float c[4], const uint32_t a[4],
                                         uint32_t b0, uint32_t b1) {
    asm volatile("mma.sync.aligned.m16n8k16.row.col.f32.f16.f16.f32 "
                 "{%0,%1,%2,%3}, {%4,%5,%6,%7}, {%8,%9}, {%0,%1,%2,%3};"
                 : "+f"(c[0]), "+f"(c[1]), "+f"(c[2]), "+f"(c[3])
                 : "r"(a[0]), "r"(a[1]), "r"(a[2]), "r"(a[3]), "r"(b0), "r"(b1));
}
__device__ __forceinline__ uint32_t packh2(float v0, float v1) {
    __half2 hp = __floats2half2_rn(v0, v1);
    return *reinterpret_cast<uint32_t*>(&hp);
}
__device__ __forceinline__ float ldgnc(const float* p) {
    float v;
    asm volatile("ld.global.nc.f32 %0, [%1];" : "=f"(v) : "l"(p));
    return v;
}

// GEMM1 B-frag ldsm addr on W[o][c]: groups = n0k0,n0k8,n8k0,n8k8
__device__ __forceinline__ uint32_t waddrB(uint32_t sbW, int ntp, int kc, int lane) {
    const int o  = ntp * 16 + ((lane >> 4) & 1) * 8 + (lane & 7);
    const int cb = kc * 32 + ((lane >> 3) & 1) * 16;
    return sbW + (uint32_t)(o * 128) + (uint32_t)(cb ^ ((o & 7) << 4));
}
// GEMM2 A-frag ldsm addr on W[o'][o]: groups = m0k0,m8k0,m0k8,m8k8
__device__ __forceinline__ uint32_t waddrA(uint32_t sbW, int mtp, int kc, int lane) {
    const int o  = mtp * 16 + ((lane >> 3) & 1) * 8 + (lane & 7);
    const int cb = kc * 32 + ((lane >> 4) & 1) * 16;
    return sbW + (uint32_t)(o * 128) + (uint32_t)(cb ^ ((o & 7) << 4));
}

__device__ __forceinline__ size_t tile_base(int t) {
    return (size_t)(t >> 12) * 4194304 + (size_t)(t & 4095) * 16;
}

// load this lane's 8 X scalars for k-chunk kc, convert to A-frag half2 x4
__device__ __forceinline__ void ldxh(const float* xb, int kc, int tq, int g,
                                     uint32_t v[4]) {
    const float* p0 = xb + (size_t)(kc * 16 + 2 * tq) * 65536 + g;
    const float a0 = ldgnc(p0),             a1 = ldgnc(p0 + 65536);
    const float a2 = ldgnc(p0 + 8),         a3 = ldgnc(p0 + 65536 + 8);
    const float* p1 = p0 + (size_t)8 * 65536;
    const float a4 = ldgnc(p1),             a5 = ldgnc(p1 + 65536);
    const float a6 = ldgnc(p1 + 8),         a7 = ldgnc(p1 + 65536 + 8);
    v[0] = packh2(a0, a1);   // (m=g,   k lo pair)
    v[1] = packh2(a2, a3);   // (m=g+8, k lo pair)
    v[2] = packh2(a4, a5);   // (m=g,   k hi pair)
    v[3] = packh2(a6, a7);   // (m=g+8, k hi pair)
}

__global__ __launch_bounds__(TPB, 1) void fused_h6(
    const float* __restrict__ x, const float* __restrict__ illu,
    const float* __restrict__ wvspec, const float* __restrict__ wvspat,
    const float* __restrict__ wproj, float* __restrict__ out)
{
    extern __shared__ char smem[];
    const uint32_t sb = smem_u32(smem);
    const int tid = threadIdx.x, lane = tid & 31, w = tid >> 5;
    const int g = lane >> 2, tq = lane & 3;

    // ---- weights -> smem fp16 (once) ----
    for (int i = tid; i < 4096; i += TPB) {
        const int o = i >> 6, c = i & 63;
        const uint32_t off = (uint32_t)(o * 128) +
                             (((uint32_t)(2 * c)) ^ ((uint32_t)(o & 7) << 4));
        *(__half*)(smem + SM_WM + off) =
            __float2half_rn(0.6f * wvspec[i] + 0.4f * wvspat[i]);
        *(__half*)(smem + SM_WP + off) = __float2half_rn(wproj[i]);
    }
    __syncthreads();

    // Wp register-resident (GEMM2 A-frags); Wm re-ldsm'd per tile in GEMM1
    uint32_t wp[16][4];   // [kc*4+mt]
    #pragma unroll
    for (int kc = 0; kc < 4; kc++)
        #pragma unroll
        for (int p = 0; p < 4; p++)
            ldsm4(waddrA(sb + SM_WP, p, kc, lane), wp[kc * 4 + p]);

    const uint32_t sbWM = sb + SM_WM;
    const uint32_t sbIL = sb + SM_ILL + (uint32_t)w * ILL_WSZ;
    const float* ILF = (const float*)(smem + SM_ILL + (size_t)w * ILL_WSZ);

    int t = blockIdx.x * NWARPS + w;
    const int stride = gridDim.x * NWARPS;
    if (t >= NWT) return;

    uint32_t xh[4][4];
    {   // prologue: X(t) -> half2 frags + illu(t) cp.async
        const float* xb = x + tile_base(t);
        #pragma unroll
        for (int kc = 0; kc < 4; kc++) ldxh(xb, kc, tq, g, xh[kc]);
        const float* ib = illu + tile_base(t);
        #pragma unroll
        for (int k = 0; k < 8; k++) {
            const int j = lane + k * 32, c = j >> 2, q = j & 3;
            cp_async16(sbIL + (uint32_t)(c * 80 + q * 16),
                       ib + (size_t)c * 65536 + q * 4);
        }
        cp_commit();
    }

    while (t < NWT) {
        const int tn = t + stride;
        const float* xbn = (tn < NWT) ? x + tile_base(tn) : x;

        // ---- GEMM1: acc1[px16][o64] = X^T @ Wm^T (Wm via ldsm here) ----
        float acc1[8][4];
        #pragma unroll
        for (int nt = 0; nt < 8; nt++)
            #pragma unroll
            for (int q = 0; q < 4; q++) acc1[nt][q] = 0.0f;

        #pragma unroll
        for (int kc = 0; kc < 4; kc++) {
            uint32_t a[4] = { xh[kc][0], xh[kc][1], xh[kc][2], xh[kc][3] };
            #pragma unroll
            for (int ntp = 0; ntp < 4; ntp++) {
                uint32_t b[4];
                ldsm4(waddrB(sbWM, ntp, kc, lane), b);
                mma16816(acc1[2 * ntp],     a, b[0], b[1]);
                mma16816(acc1[2 * ntp + 1], a, b[2], b[3]);
            }
            if (tn < NWT) ldxh(xbn, kc, tq, g, xh[kc]);  // prefetch, regs free
        }

        cp_wait<0>();
        __syncwarp();          // other lanes' illu(t) cp.async visible

        // ---- GEMM2 (swapped): acc2[o'64][px16] = Wp @ (illu * D1) ----
        // acc1 IS the B-frag source: [0][1] -> k-pair @ n=px=g,
        //                            [2][3] -> same k-pair @ n=g+8.
        float acc2[4][2][4];
        #pragma unroll
        for (int mt = 0; mt < 4; mt++)
            #pragma unroll
            for (int nt = 0; nt < 2; nt++)
                #pragma unroll
                for (int q = 0; q < 4; q++) acc2[mt][nt][q] = 0.0f;

        #pragma unroll
        for (int kc = 0; kc < 4; kc++) {
            const int nA = 2 * kc, nB = 2 * kc + 1;
            const int o0 = nA * 8 + 2 * tq;
            const int o8 = nB * 8 + 2 * tq;
            uint32_t blo[2], bhi[2];
            blo[0] = packh2(acc1[nA][0] * ILF[o0 * 20 + g],
                            acc1[nA][1] * ILF[(o0 + 1) * 20 + g]);
            blo[1] = packh2(acc1[nB][0] * ILF[o8 * 20 + g],
                            acc1[nB][1] * ILF[(o8 + 1) * 20 + g]);
            bhi[0] = packh2(acc1[nA][2] * ILF[o0 * 20 + g + 8],
                            acc1[nA][3] * ILF[(o0 + 1) * 20 + g + 8]);
            bhi[1] = packh2(acc1[nB][2] * ILF[o8 * 20 + g + 8],
                            acc1[nB][3] * ILF[(o8 + 1) * 20 + g + 8]);
            #pragma unroll
            for (int mt = 0; mt < 4; mt++) {
                const uint32_t* aW = wp[kc * 4 + mt];
                mma16816(acc2[mt][0], aW, blo[0], blo[1]);
                mma16816(acc2[mt][1], aW, bhi[0], bhi[1]);
            }
        }
        __syncwarp();          // all lanes done reading illu(t)

        // prefetch illu(t+1) (single buffer: safe only after reads done)
        if (tn < NWT) {
            const float* ib = illu + tile_base(tn);
            #pragma unroll
            for (int k = 0; k < 8; k++) {
                const int j = lane + k * 32, c = j >> 2, q = j & 3;
                cp_async16(sbIL + (uint32_t)(c * 80 + q * 16),
                           ib + (size_t)c * 65536 + q * 4);
            }
            cp_commit();
        }

        // ---- store: acc2 (m=o', n=px) -> float2 per lane ----
        {
            float* obp = out + tile_base(t);
            #pragma unroll
            for (int mt = 0; mt < 4; mt++)
                #pragma unroll
                for (int nt = 0; nt < 2; nt++) {
                    const int o0 = mt * 16 + g;
                    const int px = nt * 8 + 2 * tq;
                    *(float2*)(obp + (size_t)o0 * 65536 + px) =
                        make_float2(acc2[mt][nt][0], acc2[mt][nt][1]);
                    *(float2*)(obp + (size_t)(o0 + 8) * 65536 + px) =
                        make_float2(acc2[mt][nt][2], acc2[mt][nt][3]);
                }
        }
        t = tn;
    }
}

extern "C" void kernel_launch(void* const* d_in, const int* in_sizes, int n_in,
                              void* d_out, int out_size)
{
    const float* x      = (const float*)d_in[0];
    const float* illu   = (const float*)d_in[1];
    const float* wvspec = (const float*)d_in[4];
    const float* wvspat = (const float*)d_in[7];
    const float* wproj  = (const float*)d_in[10];
    float* out = (float*)d_out;

    int dev = 0, sms = 148;
    cudaGetDevice(&dev);
    cudaDeviceGetAttribute(&sms, cudaDevAttrMultiProcessorCount, dev);
    if (sms < 1) sms = 148;
    int grid = sms;                      // 1 CTA/SM
    if (grid * NWARPS > NWT) grid = NWT / NWARPS;

    cudaFuncSetAttribute(fused_h6, cudaFuncAttributeMaxDynamicSharedMemorySize,
                         SM_TOTAL);
    fused_h6<<<grid, TPB, SM_TOTAL>>>(x, illu, wvspec, wvspat, wproj, out);
}